// round 2
// baseline (speedup 1.0000x reference)
#include <cuda_runtime.h>
#include <math.h>

#define NPTS  1024
#define D2    256
#define D3    512
#define CELLS 64
#define SBCNT 128

__device__ float g_hsum[SBCNT * CELLS * D2];
__device__ int   g_cnt [SBCNT * CELLS];

__constant__ float c_freq[8] = {
    1.0f, 1.7782794100389228f, 3.1622776601683795f, 5.623413251903491f,
    10.0f, 17.782794100389228f, 31.622776601683793f, 56.23413251903491f
};

typedef unsigned long long u64;

__device__ __forceinline__ u64 pk2(float lo, float hi) {
    u64 r; asm("mov.b64 %0,{%1,%2};" : "=l"(r) : "f"(lo), "f"(hi)); return r;
}
__device__ __forceinline__ u64 dup2(float v) { return pk2(v, v); }
__device__ __forceinline__ u64 ffma2(u64 a, u64 b, u64 c) {
    u64 d; asm("fma.rn.f32x2 %0,%1,%2,%3;" : "=l"(d) : "l"(a), "l"(b), "l"(c)); return d;
}
__device__ __forceinline__ float2 un2(u64 v) {
    float2 f; asm("mov.b64 {%0,%1},%2;" : "=f"(f.x), "=f"(f.y) : "l"(v)); return f;
}
__device__ __forceinline__ float silu_f(float v) {
    return __fdividef(v, 1.0f + __expf(-v));
}
// trig of fp32 arg with double mod-2pi reduction (fast-math safe)
__device__ __forceinline__ float trig_red(float arg, int use_cos) {
    double d = (double)arg;
    double q = rint(d * 0.15915494309189535);
    float r = (float)fma(-q, 6.283185307179586, d);
    return use_cos ? cosf(r) : sinf(r);
}

// ---------------- K1 smem layout (bytes) ----------------
#define S1_W2    0          // 131072
#define S1_B1    131072     // 512
#define S1_B2    131584     // 1024
#define S1_ACC   132608     // 65536
#define S1_H1    198144     // 16384 (8 warps * 4 pts * 128 f)
#define S1_CELL  214528     // 4096
#define S1_ORD   218624     // 4096
#define S1_CNT   222720     // 256
#define S1_START 222976     // 272
#define S1_CUR   223248     // 256
#define SMEM1    223504

__global__ __launch_bounds__(256, 1)
void k1_embed_agg(const float* __restrict__ ds, const float* __restrict__ de,
                  const float* __restrict__ W1, const float* __restrict__ b1,
                  const float* __restrict__ W2, const float* __restrict__ b2)
{
    extern __shared__ char smem[];
    float*    W2s    = (float*)(smem + S1_W2);
    float*    b1s    = (float*)(smem + S1_B1);
    float*    b2s    = (float*)(smem + S1_B2);
    float*    accum  = (float*)(smem + S1_ACC);
    float*    h1s    = (float*)(smem + S1_H1);
    unsigned* cellsm = (unsigned*)(smem + S1_CELL);
    unsigned* ordsm  = (unsigned*)(smem + S1_ORD);
    unsigned* cntsm  = (unsigned*)(smem + S1_CNT);
    unsigned* startsm= (unsigned*)(smem + S1_START);
    unsigned* cursm  = (unsigned*)(smem + S1_CUR);

    const int tid = threadIdx.x;
    const int w   = tid >> 5;
    const int l   = tid & 31;
    const int sb  = blockIdx.x;
    const int side = sb >> 6;
    const int bv   = sb & 63;
    const float* __restrict__ drags = (side ? de : ds) + (size_t)bv * NPTS * 2;

    // stage W2, biases; zero counters
    {
        const float4* W24 = (const float4*)W2;
        float4* W2s4 = (float4*)W2s;
        #pragma unroll 4
        for (int i = tid; i < (128 * 256) / 4; i += 256) W2s4[i] = W24[i];
        if (tid < 128) b1s[tid] = b1[tid];
        if (tid < 256) b2s[tid] = b2[tid];
        if (tid < 64)  cntsm[tid] = 0u;
    }
    __syncthreads();

    // pass 1: cells + counts
    for (int i = tid; i < NPTS; i += 256) {
        float x = drags[2 * i], y = drags[2 * i + 1];
        unsigned cell = (unsigned)((((int)x) >> 6) * 8 + (((int)y) >> 6));
        cellsm[i] = cell;
        atomicAdd(&cntsm[cell], 1u);
    }
    __syncthreads();
    if (tid == 0) {
        unsigned run = 0;
        for (int c = 0; c < CELLS; c++) { startsm[c] = run; run += cntsm[c]; }
        startsm[CELLS] = run;
    }
    __syncthreads();
    if (tid < 64) {
        cursm[tid] = startsm[tid];
        g_cnt[sb * CELLS + tid] = (int)cntsm[tid];
    }
    __syncthreads();
    // scatter to sorted order; zero accum in parallel
    for (int i = tid; i < NPTS; i += 256) {
        unsigned pos = atomicAdd(&cursm[cellsm[i]], 1u);
        ordsm[pos] = i;
    }
    {
        float4* ac4 = (float4*)accum;
        for (int i = tid; i < (CELLS * D2) / 4; i += 256)
            ac4[i] = make_float4(0.f, 0.f, 0.f, 0.f);
    }
    __syncthreads();

    // compute: warp w owns cells [8w, 8w+8)
    const unsigned pbeg = startsm[8 * w];
    const unsigned pend = startsm[8 * w + 8];
    float* myh1 = h1s + w * 512;

    const float fr      = c_freq[l >> 2];
    const int   use_y   = l & 1;
    const int   use_cos = (l >> 1) & 1;

    for (unsigned p0 = pbeg; p0 < pend; p0 += 4) {
        const int nv = (int)min(4u, pend - p0);
        float fv[4]; int cel[4];
        #pragma unroll
        for (int pp = 0; pp < 4; pp++) {
            float x = 0.f, y = 0.f;
            if (pp < nv) {
                unsigned idx = ordsm[p0 + pp];
                x = drags[2 * idx]; y = drags[2 * idx + 1];
                cel[pp] = (((int)x) >> 6) * 8 + (((int)y) >> 6);
            } else cel[pp] = -1;
            float arg = (use_y ? y : x) * fr;
            fv[pp] = trig_red(arg, use_cos);
        }

        // L1: lane owns cols [4l, 4l+4)
        u64 a1[4][2];
        {
            u64 bb0 = *(const u64*)(b1s + 4 * l);
            u64 bb1 = *(const u64*)(b1s + 4 * l + 2);
            #pragma unroll
            for (int pp = 0; pp < 4; pp++) { a1[pp][0] = bb0; a1[pp][1] = bb1; }
        }
        #pragma unroll 4
        for (int k = 0; k < 32; k++) {
            const u64* wp = (const u64*)(W1 + k * 128 + 4 * l);
            u64 w0 = wp[0], w1v = wp[1];
            #pragma unroll
            for (int pp = 0; pp < 4; pp++) {
                u64 f2 = dup2(__shfl_sync(0xffffffffu, fv[pp], k));
                a1[pp][0] = ffma2(f2, w0,  a1[pp][0]);
                a1[pp][1] = ffma2(f2, w1v, a1[pp][1]);
            }
        }
        #pragma unroll
        for (int pp = 0; pp < 4; pp++) {
            float2 v0 = un2(a1[pp][0]), v1 = un2(a1[pp][1]);
            float4 hv = make_float4(silu_f(v0.x), silu_f(v0.y),
                                    silu_f(v1.x), silu_f(v1.y));
            *(float4*)(myh1 + pp * 128 + 4 * l) = hv;
        }
        __syncwarp();

        // L2: lane owns col pairs (2l + 64j), j=0..3
        u64 a2[4][4];
        #pragma unroll
        for (int j = 0; j < 4; j++) {
            u64 bb = *(const u64*)(b2s + 2 * l + 64 * j);
            #pragma unroll
            for (int pp = 0; pp < 4; pp++) a2[pp][j] = bb;
        }
        #pragma unroll 4
        for (int k = 0; k < 128; k++) {
            const float* wrow = W2s + k * 256 + 2 * l;
            u64 wv0 = *(const u64*)(wrow);
            u64 wv1 = *(const u64*)(wrow + 64);
            u64 wv2 = *(const u64*)(wrow + 128);
            u64 wv3 = *(const u64*)(wrow + 192);
            #pragma unroll
            for (int pp = 0; pp < 4; pp++) {
                u64 hd = dup2(myh1[pp * 128 + k]);
                a2[pp][0] = ffma2(hd, wv0, a2[pp][0]);
                a2[pp][1] = ffma2(hd, wv1, a2[pp][1]);
                a2[pp][2] = ffma2(hd, wv2, a2[pp][2]);
                a2[pp][3] = ffma2(hd, wv3, a2[pp][3]);
            }
        }

        // silu + race-free accumulate (warp owns its cells)
        #pragma unroll
        for (int pp = 0; pp < 4; pp++) {
            if (cel[pp] >= 0) {
                float* ac = accum + cel[pp] * 256 + 2 * l;
                #pragma unroll
                for (int j = 0; j < 4; j++) {
                    float2 v = un2(a2[pp][j]);
                    float2* ap = (float2*)(ac + 64 * j);
                    float2 cur = *ap;
                    cur.x += silu_f(v.x);
                    cur.y += silu_f(v.y);
                    *ap = cur;
                }
            }
        }
        __syncwarp();
    }
    __syncthreads();

    {
        float4* dst = (float4*)(g_hsum + (size_t)sb * CELLS * D2);
        const float4* src = (const float4*)accum;
        for (int i = tid; i < (CELLS * D2) / 4; i += 256) dst[i] = src[i];
    }
}

// ---------------- K2 smem layout ----------------
#define S2_W3T 0        // 131072 (64 rows * 512 f)
#define S2_HST 131072   // 66560  (256 * 65 f, padded transpose)
#define S2_B3  197632   // 2048
#define S2_CNT 199680   // 256
#define SMEM2  199936

// out[cell-major] = Hsum @ W3 + cnt*b3.  Warp w owns cols [32w,32w+32),
// lane l owns cells l and l+32.
__global__ __launch_bounds__(512, 1)
void k2_l3(const float* __restrict__ W3, const float* __restrict__ b3,
           float* __restrict__ out)
{
    extern __shared__ char smem[];
    float* w3t  = (float*)(smem + S2_W3T);
    float* Hst  = (float*)(smem + S2_HST);
    float* b3s  = (float*)(smem + S2_B3);
    float* cnts = (float*)(smem + S2_CNT);

    const int tid = threadIdx.x;
    const int w   = tid >> 5;
    const int l   = tid & 31;
    const int sb  = blockIdx.x;
    const int side = sb >> 6;
    const int bv   = sb & 63;

    // stage transposed H: Hst[k*65 + cell] = g_hsum[sb][cell][k]
    {
        const float* src = g_hsum + (size_t)sb * CELLS * D2;
        for (int base = tid; base < CELLS * D2; base += 512) {
            int cell = base >> 8;       // /256
            int k    = base & 255;
            Hst[k * 65 + cell] = src[base];
        }
        if (tid < 512) b3s[tid] = b3[tid];
        if (tid < 64)  cnts[tid] = (float)g_cnt[sb * CELLS + tid];
    }

    u64 acc[2][16];
    #pragma unroll
    for (int h = 0; h < 2; h++)
        #pragma unroll
        for (int j = 0; j < 16; j++) acc[h][j] = 0ull;

    for (int kt = 0; kt < 4; kt++) {
        __syncthreads();
        {
            const float4* src = (const float4*)(W3 + (size_t)kt * 64 * D3);
            float4* dst = (float4*)w3t;
            #pragma unroll 4
            for (int i = tid; i < (64 * D3) / 4; i += 512) dst[i] = src[i];
        }
        __syncthreads();
        #pragma unroll 2
        for (int kk = 0; kk < 64; kk++) {
            const int k = kt * 64 + kk;
            u64 hd0 = dup2(Hst[k * 65 + l]);
            u64 hd1 = dup2(Hst[k * 65 + l + 32]);
            const float* wr = w3t + kk * D3 + 32 * w;
            #pragma unroll
            for (int j = 0; j < 16; j++) {
                u64 wv = *(const u64*)(wr + 2 * j);
                acc[0][j] = ffma2(hd0, wv, acc[0][j]);
                acc[1][j] = ffma2(hd1, wv, acc[1][j]);
            }
        }
    }

    const float c0 = cnts[l], c1 = cnts[l + 32];
    float* outp = out + ((size_t)(bv * 1024 + side * 512)) * 64;
    #pragma unroll
    for (int j = 0; j < 16; j++) {
        int col = 32 * w + 2 * j;
        float bx = b3s[col], by = b3s[col + 1];
        float2 v0 = un2(acc[0][j]);
        float2 v1 = un2(acc[1][j]);
        outp[(size_t)col       * 64 + l]      = v0.x + c0 * bx;
        outp[(size_t)(col + 1) * 64 + l]      = v0.y + c0 * by;
        outp[(size_t)col       * 64 + l + 32] = v1.x + c1 * bx;
        outp[(size_t)(col + 1) * 64 + l + 32] = v1.y + c1 * by;
    }
}

extern "C" void kernel_launch(void* const* d_in, const int* in_sizes, int n_in,
                              void* d_out, int out_size)
{
    const float* ds = (const float*)d_in[0];
    const float* de = (const float*)d_in[1];
    const float* W1 = (const float*)d_in[2];
    const float* b1 = (const float*)d_in[3];
    const float* W2 = (const float*)d_in[4];
    const float* b2 = (const float*)d_in[5];
    const float* W3 = (const float*)d_in[6];
    const float* b3 = (const float*)d_in[7];
    float* out = (float*)d_out;

    cudaFuncSetAttribute(k1_embed_agg, cudaFuncAttributeMaxDynamicSharedMemorySize, SMEM1);
    cudaFuncSetAttribute(k2_l3,        cudaFuncAttributeMaxDynamicSharedMemorySize, SMEM2);

    k1_embed_agg<<<SBCNT, 256, SMEM1>>>(ds, de, W1, b1, W2, b2);
    k2_l3<<<SBCNT, 512, SMEM2>>>(W3, b3, out);
}

// round 3
// speedup vs baseline: 1.0850x; 1.0850x over previous
#include <cuda_runtime.h>
#include <math.h>

#define NPTS  1024
#define D2    256
#define D3    512
#define CELLS 64
#define SBCNT 128

__device__ float g_hsum[SBCNT * CELLS * D2];
__device__ int   g_cnt [SBCNT * CELLS];

__constant__ float c_freq[8] = {
    1.0f, 1.7782794100389228f, 3.1622776601683795f, 5.623413251903491f,
    10.0f, 17.782794100389228f, 31.622776601683793f, 56.23413251903491f
};

typedef unsigned long long u64;

__device__ __forceinline__ u64 pk2(float lo, float hi) {
    u64 r; asm("mov.b64 %0,{%1,%2};" : "=l"(r) : "f"(lo), "f"(hi)); return r;
}
__device__ __forceinline__ u64 dup2(float v) { return pk2(v, v); }
__device__ __forceinline__ u64 ffma2(u64 a, u64 b, u64 c) {
    u64 d; asm("fma.rn.f32x2 %0,%1,%2,%3;" : "=l"(d) : "l"(a), "l"(b), "l"(c)); return d;
}
__device__ __forceinline__ u64 fadd2(u64 a, u64 b) {
    u64 d; asm("add.rn.f32x2 %0,%1,%2;" : "=l"(d) : "l"(a), "l"(b)); return d;
}
__device__ __forceinline__ float2 un2(u64 v) {
    float2 f; asm("mov.b64 {%0,%1},%2;" : "=f"(f.x), "=f"(f.y) : "l"(v)); return f;
}
__device__ __forceinline__ float silu_f(float v) {
    return __fdividef(v, 1.0f + __expf(-v));
}
__device__ __forceinline__ u64 silu2(u64 a) {
    float2 v = un2(a); return pk2(silu_f(v.x), silu_f(v.y));
}
// fp32 Cody-Waite mod-2pi reduction (args <= ~41000)
__device__ __forceinline__ float trig_red(float arg, int use_cos) {
    const float INV2PI = 0.15915494309189535f;
    const float C_HI   = 6.2831854820251465f;
    const float C_LO   = -1.7484556e-7f;
    float q = rintf(arg * INV2PI);
    float r = __fmaf_rn(-q, C_HI, arg);
    r = __fmaf_rn(-q, C_LO, r);
    return use_cos ? cosf(r) : sinf(r);
}

// ---------------- K1 smem layout (bytes) ----------------
#define S1_W2    0          // 131072
#define S1_W1    131072     // 16384
#define S1_H1    147456     // 32768  (8 warps * 8 pts * 128 f)
#define S1_ORD   180224     // 2048   (u16[1024])
#define S1_CNT   182272     // 256
#define S1_START 182528     // 272
#define S1_CUR   182800     // 256
#define SMEM1    183056

__global__ __launch_bounds__(256, 1)
void k1_embed_agg(const float* __restrict__ ds, const float* __restrict__ de,
                  const float* __restrict__ W1, const float* __restrict__ b1,
                  const float* __restrict__ W2, const float* __restrict__ b2)
{
    extern __shared__ char smem[];
    float*          W2s    = (float*)(smem + S1_W2);
    float*          W1s    = (float*)(smem + S1_W1);
    float*          h1s    = (float*)(smem + S1_H1);
    unsigned short* ordsm  = (unsigned short*)(smem + S1_ORD);
    unsigned*       cntsm  = (unsigned*)(smem + S1_CNT);
    unsigned*       startsm= (unsigned*)(smem + S1_START);
    unsigned*       cursm  = (unsigned*)(smem + S1_CUR);

    const int tid = threadIdx.x;
    const int w   = tid >> 5;
    const int l   = tid & 31;
    const int sb  = blockIdx.x;
    const int side = sb >> 6;
    const int bv   = sb & 63;
    const float* __restrict__ drags = (side ? de : ds) + (size_t)bv * NPTS * 2;

    // stage W2, W1; zero counters
    {
        const float4* src2 = (const float4*)W2;
        float4* dst2 = (float4*)W2s;
        #pragma unroll 4
        for (int i = tid; i < (128 * 256) / 4; i += 256) dst2[i] = src2[i];
        const float4* src1 = (const float4*)W1;
        float4* dst1 = (float4*)W1s;
        #pragma unroll
        for (int i = tid; i < (32 * 128) / 4; i += 256) dst1[i] = src1[i];
        if (tid < 64) cntsm[tid] = 0u;
    }
    __syncthreads();

    // pass 1: counts
    for (int i = tid; i < NPTS; i += 256) {
        float x = drags[2 * i], y = drags[2 * i + 1];
        unsigned cell = (unsigned)((((int)x) >> 6) * 8 + (((int)y) >> 6));
        atomicAdd(&cntsm[cell], 1u);
    }
    __syncthreads();
    if (tid == 0) {
        unsigned run = 0;
        for (int c = 0; c < CELLS; c++) { startsm[c] = run; run += cntsm[c]; }
        startsm[CELLS] = run;
    }
    __syncthreads();
    if (tid < 64) {
        cursm[tid] = startsm[tid];
        g_cnt[sb * CELLS + tid] = (int)cntsm[tid];
    }
    __syncthreads();
    // pass 2: scatter to sorted order
    for (int i = tid; i < NPTS; i += 256) {
        float x = drags[2 * i], y = drags[2 * i + 1];
        unsigned cell = (unsigned)((((int)x) >> 6) * 8 + (((int)y) >> 6));
        unsigned pos = atomicAdd(&cursm[cell], 1u);
        ordsm[pos] = (unsigned short)i;
    }
    __syncthreads();

    // per-lane bias registers
    u64 b1r0 = *(const u64*)(b1 + 4 * l);
    u64 b1r1 = *(const u64*)(b1 + 4 * l + 2);
    u64 b2r[4];
    #pragma unroll
    for (int j = 0; j < 4; j++) b2r[j] = *(const u64*)(b2 + 2 * l + 64 * j);

    // compute: warp w owns cells [8w, 8w+8)
    const unsigned pbeg = startsm[8 * w];
    const unsigned pend = startsm[8 * w + 8];
    float* myh1 = h1s + w * 1024;

    const float fr      = c_freq[l >> 2];
    const int   use_y   = l & 1;
    const int   use_cos = (l >> 1) & 1;

    u64 run0 = 0, run1 = 0, run2 = 0, run3 = 0;
    int cur_cell = -1;
    float* gbase = g_hsum + ((size_t)sb * CELLS) * D2 + 2 * l;

    for (unsigned p0 = pbeg; p0 < pend; p0 += 8) {
        const int nv = (int)min(8u, pend - p0);
        float fv[8]; int cel[8];
        #pragma unroll
        for (int pp = 0; pp < 8; pp++) {
            float x = 0.f, y = 0.f;
            if (pp < nv) {
                int idx = (int)ordsm[p0 + pp];
                x = drags[2 * idx]; y = drags[2 * idx + 1];
                cel[pp] = (((int)x) >> 6) * 8 + (((int)y) >> 6);
            } else cel[pp] = -1;
            fv[pp] = trig_red((use_y ? y : x) * fr, use_cos);
        }

        // ---- L1: lane owns cols [4l, 4l+4) ----
        u64 a1[8][2];
        #pragma unroll
        for (int pp = 0; pp < 8; pp++) { a1[pp][0] = b1r0; a1[pp][1] = b1r1; }
        #pragma unroll 8
        for (int k = 0; k < 32; k++) {
            const u64* wp = (const u64*)(W1s + k * 128 + 4 * l);
            u64 w0 = wp[0], w1v = wp[1];
            #pragma unroll
            for (int pp = 0; pp < 8; pp++) {
                u64 f2 = dup2(__shfl_sync(0xffffffffu, fv[pp], k));
                a1[pp][0] = ffma2(f2, w0,  a1[pp][0]);
                a1[pp][1] = ffma2(f2, w1v, a1[pp][1]);
            }
        }
        #pragma unroll
        for (int pp = 0; pp < 8; pp++) {
            float2 v0 = un2(a1[pp][0]), v1 = un2(a1[pp][1]);
            float4 hv = make_float4(silu_f(v0.x), silu_f(v0.y),
                                    silu_f(v1.x), silu_f(v1.y));
            *(float4*)(myh1 + pp * 128 + 4 * l) = hv;
        }
        __syncwarp();

        // ---- L2: lane owns col pairs (2l + 64j), j=0..3 ----
        u64 a2[8][4];
        #pragma unroll
        for (int pp = 0; pp < 8; pp++) {
            a2[pp][0] = b2r[0]; a2[pp][1] = b2r[1];
            a2[pp][2] = b2r[2]; a2[pp][3] = b2r[3];
        }
        #pragma unroll 2
        for (int kp = 0; kp < 64; kp++) {
            float2 hpv[8];
            #pragma unroll
            for (int pp = 0; pp < 8; pp++)
                hpv[pp] = *(const float2*)(myh1 + pp * 128 + 2 * kp);
            #pragma unroll
            for (int s = 0; s < 2; s++) {
                const float* wrow = W2s + (2 * kp + s) * 256 + 2 * l;
                u64 wv0 = *(const u64*)(wrow);
                u64 wv1 = *(const u64*)(wrow + 64);
                u64 wv2 = *(const u64*)(wrow + 128);
                u64 wv3 = *(const u64*)(wrow + 192);
                #pragma unroll
                for (int pp = 0; pp < 8; pp++) {
                    u64 hd = dup2(s ? hpv[pp].y : hpv[pp].x);
                    a2[pp][0] = ffma2(hd, wv0, a2[pp][0]);
                    a2[pp][1] = ffma2(hd, wv1, a2[pp][1]);
                    a2[pp][2] = ffma2(hd, wv2, a2[pp][2]);
                    a2[pp][3] = ffma2(hd, wv3, a2[pp][3]);
                }
            }
        }

        // ---- silu + run-accumulate (cell is warp-uniform; sorted order) ----
        for (int pp = 0; pp < 8; pp++) {
            if (cel[pp] < 0) break;
            if (cel[pp] != cur_cell) {
                if (cur_cell >= 0) {
                    float* gp = gbase + (size_t)cur_cell * D2;
                    *(float2*)(gp)       = un2(run0);
                    *(float2*)(gp + 64)  = un2(run1);
                    *(float2*)(gp + 128) = un2(run2);
                    *(float2*)(gp + 192) = un2(run3);
                }
                cur_cell = cel[pp];
                run0 = run1 = run2 = run3 = 0;
            }
            run0 = fadd2(run0, silu2(a2[pp][0]));
            run1 = fadd2(run1, silu2(a2[pp][1]));
            run2 = fadd2(run2, silu2(a2[pp][2]));
            run3 = fadd2(run3, silu2(a2[pp][3]));
        }
        __syncwarp();
    }
    if (cur_cell >= 0) {
        float* gp = gbase + (size_t)cur_cell * D2;
        *(float2*)(gp)       = un2(run0);
        *(float2*)(gp + 64)  = un2(run1);
        *(float2*)(gp + 128) = un2(run2);
        *(float2*)(gp + 192) = un2(run3);
    }
    // zero-fill empty cells
    #pragma unroll
    for (int c = 8 * w; c < 8 * w + 8; c++) {
        if (cntsm[c] == 0u) {
            float* gp = gbase + (size_t)c * D2;
            float2 z = make_float2(0.f, 0.f);
            *(float2*)(gp)       = z;
            *(float2*)(gp + 64)  = z;
            *(float2*)(gp + 128) = z;
            *(float2*)(gp + 192) = z;
        }
    }
}

// ---------------- K2 smem layout ----------------
#define S2_HST 0        // 66560 (256 * 65 f, padded transpose)
#define S2_B3  66560    // 2048
#define S2_CNT 68608    // 256
#define SMEM2  68864

// out = Hsum @ W3 + cnt*b3.  Warp w owns cols [32w,32w+32); lane l owns
// cells l, l+32. W3 streamed from gmem (warp-uniform LDG.128, L1-cached).
__global__ __launch_bounds__(512, 1)
void k2_l3(const float* __restrict__ W3, const float* __restrict__ b3,
           float* __restrict__ out)
{
    extern __shared__ char smem[];
    float* Hst  = (float*)(smem + S2_HST);
    float* b3s  = (float*)(smem + S2_B3);
    float* cnts = (float*)(smem + S2_CNT);

    const int tid = threadIdx.x;
    const int w   = tid >> 5;
    const int l   = tid & 31;
    const int sb  = blockIdx.x;
    const int side = sb >> 6;
    const int bv   = sb & 63;

    // stage transposed H: Hst[k*65 + cell] = g_hsum[sb][cell][k]
    {
        const float* src = g_hsum + (size_t)sb * CELLS * D2;
        for (int base = tid; base < CELLS * D2; base += 512) {
            int cell = base >> 8;
            int k    = base & 255;
            Hst[k * 65 + cell] = src[base];
        }
        b3s[tid] = b3[tid];
        if (tid < 64) cnts[tid] = (float)g_cnt[sb * CELLS + tid];
    }
    __syncthreads();

    u64 acc[2][16];
    #pragma unroll
    for (int h = 0; h < 2; h++)
        #pragma unroll
        for (int j = 0; j < 16; j++) acc[h][j] = 0ull;

    const float4* __restrict__ wbase = (const float4*)(W3 + 32 * w);
    #pragma unroll 2
    for (int k = 0; k < 256; k++) {
        u64 hd0 = dup2(Hst[k * 65 + l]);
        u64 hd1 = dup2(Hst[k * 65 + l + 32]);
        const float4* wr = wbase + k * (D3 / 4);
        #pragma unroll
        for (int j4 = 0; j4 < 8; j4++) {
            float4 wv = __ldg(wr + j4);
            u64 w01 = pk2(wv.x, wv.y);
            u64 w23 = pk2(wv.z, wv.w);
            acc[0][2 * j4]     = ffma2(hd0, w01, acc[0][2 * j4]);
            acc[0][2 * j4 + 1] = ffma2(hd0, w23, acc[0][2 * j4 + 1]);
            acc[1][2 * j4]     = ffma2(hd1, w01, acc[1][2 * j4]);
            acc[1][2 * j4 + 1] = ffma2(hd1, w23, acc[1][2 * j4 + 1]);
        }
    }

    const float c0 = cnts[l], c1 = cnts[l + 32];
    float* outp = out + ((size_t)(bv * 1024 + side * 512)) * 64;
    #pragma unroll
    for (int j = 0; j < 16; j++) {
        int col = 32 * w + 2 * j;
        float bx = b3s[col], by = b3s[col + 1];
        float2 v0 = un2(acc[0][j]);
        float2 v1 = un2(acc[1][j]);
        outp[(size_t)col       * 64 + l]      = v0.x + c0 * bx;
        outp[(size_t)(col + 1) * 64 + l]      = v0.y + c0 * by;
        outp[(size_t)col       * 64 + l + 32] = v1.x + c1 * bx;
        outp[(size_t)(col + 1) * 64 + l + 32] = v1.y + c1 * by;
    }
}

extern "C" void kernel_launch(void* const* d_in, const int* in_sizes, int n_in,
                              void* d_out, int out_size)
{
    const float* ds = (const float*)d_in[0];
    const float* de = (const float*)d_in[1];
    const float* W1 = (const float*)d_in[2];
    const float* b1 = (const float*)d_in[3];
    const float* W2 = (const float*)d_in[4];
    const float* b2 = (const float*)d_in[5];
    const float* W3 = (const float*)d_in[6];
    const float* b3 = (const float*)d_in[7];
    float* out = (float*)d_out;

    cudaFuncSetAttribute(k1_embed_agg, cudaFuncAttributeMaxDynamicSharedMemorySize, SMEM1);
    cudaFuncSetAttribute(k2_l3,        cudaFuncAttributeMaxDynamicSharedMemorySize, SMEM2);

    k1_embed_agg<<<SBCNT, 256, SMEM1>>>(ds, de, W1, b1, W2, b2);
    k2_l3<<<SBCNT, 512, SMEM2>>>(W3, b3, out);
}

// round 4
// speedup vs baseline: 1.1866x; 1.0937x over previous
#include <cuda_runtime.h>
#include <math.h>

#define NPTS  1024
#define D2    256
#define D3    512
#define CELLS 64
#define SBCNT 128

__device__ float g_hsum[SBCNT * CELLS * D2];
__device__ int   g_cnt [SBCNT * CELLS];

__constant__ float c_freq[8] = {
    1.0f, 1.7782794100389228f, 3.1622776601683795f, 5.623413251903491f,
    10.0f, 17.782794100389228f, 31.622776601683793f, 56.23413251903491f
};

typedef unsigned long long u64;

__device__ __forceinline__ u64 pk2(float lo, float hi) {
    u64 r; asm("mov.b64 %0,{%1,%2};" : "=l"(r) : "f"(lo), "f"(hi)); return r;
}
__device__ __forceinline__ u64 dup2(float v) { return pk2(v, v); }
__device__ __forceinline__ u64 ffma2(u64 a, u64 b, u64 c) {
    u64 d; asm("fma.rn.f32x2 %0,%1,%2,%3;" : "=l"(d) : "l"(a), "l"(b), "l"(c)); return d;
}
__device__ __forceinline__ u64 fadd2(u64 a, u64 b) {
    u64 d; asm("add.rn.f32x2 %0,%1,%2;" : "=l"(d) : "l"(a), "l"(b)); return d;
}
__device__ __forceinline__ float2 un2(u64 v) {
    float2 f; asm("mov.b64 {%0,%1},%2;" : "=f"(f.x), "=f"(f.y) : "l"(v)); return f;
}
__device__ __forceinline__ float silu_f(float v) {
    return __fdividef(v, 1.0f + __expf(-v));
}
__device__ __forceinline__ u64 silu2(u64 a) {
    float2 v = un2(a); return pk2(silu_f(v.x), silu_f(v.y));
}
// Cody-Waite mod-2pi then MUFU trig (arg reduced to [-pi,pi])
__device__ __forceinline__ float trig_red(float arg, int use_cos) {
    const float INV2PI = 0.15915494309189535f;
    const float C_HI   = 6.2831854820251465f;
    const float C_LO   = -1.7484556e-7f;
    float q = rintf(arg * INV2PI);
    float r = __fmaf_rn(-q, C_HI, arg);
    r = __fmaf_rn(-q, C_LO, r);
    return use_cos ? __cosf(r) : __sinf(r);
}

// ---------------- K1 smem layout (bytes) ----------------
#define S1_W2    0          // 131072
#define S1_W1    131072     // 16384
#define S1_H1    147456     // 65536  (16 warps * 8 pts * 128 f)
#define S1_ORD   212992     // 2048   (u16[1024])
#define S1_CNT   215040     // 256
#define S1_START 215296     // 272
#define S1_CUR   215568     // 256
#define SMEM1    215824

__global__ __launch_bounds__(512, 1)
void k1_embed_agg(const float* __restrict__ ds, const float* __restrict__ de,
                  const float* __restrict__ W1, const float* __restrict__ b1,
                  const float* __restrict__ W2, const float* __restrict__ b2)
{
    extern __shared__ char smem[];
    float*          W2s    = (float*)(smem + S1_W2);
    float*          W1s    = (float*)(smem + S1_W1);
    float*          h1s    = (float*)(smem + S1_H1);
    unsigned short* ordsm  = (unsigned short*)(smem + S1_ORD);
    unsigned*       cntsm  = (unsigned*)(smem + S1_CNT);
    unsigned*       startsm= (unsigned*)(smem + S1_START);
    unsigned*       cursm  = (unsigned*)(smem + S1_CUR);

    const int tid = threadIdx.x;
    const int w   = tid >> 5;
    const int l   = tid & 31;
    const int sb  = blockIdx.x;
    const int side = sb >> 6;
    const int bv   = sb & 63;
    const float* __restrict__ drags = (side ? de : ds) + (size_t)bv * NPTS * 2;

    // stage W2, W1; zero counters
    {
        const float4* src2 = (const float4*)W2;
        float4* dst2 = (float4*)W2s;
        #pragma unroll 4
        for (int i = tid; i < (128 * 256) / 4; i += 512) dst2[i] = src2[i];
        const float4* src1 = (const float4*)W1;
        float4* dst1 = (float4*)W1s;
        #pragma unroll
        for (int i = tid; i < (32 * 128) / 4; i += 512) dst1[i] = src1[i];
        if (tid < 64) cntsm[tid] = 0u;
    }
    __syncthreads();

    // counting sort: pass 1
    #pragma unroll
    for (int i = tid; i < NPTS; i += 512) {
        float2 xy = *(const float2*)(drags + 2 * i);
        unsigned cell = (unsigned)((((int)xy.x) >> 6) * 8 + (((int)xy.y) >> 6));
        atomicAdd(&cntsm[cell], 1u);
    }
    __syncthreads();
    if (tid == 0) {
        unsigned run = 0;
        for (int c = 0; c < CELLS; c++) { startsm[c] = run; run += cntsm[c]; }
        startsm[CELLS] = run;
    }
    __syncthreads();
    if (tid < 64) {
        cursm[tid] = startsm[tid];
        g_cnt[sb * CELLS + tid] = (int)cntsm[tid];
    }
    __syncthreads();
    // pass 2: scatter to sorted order
    #pragma unroll
    for (int i = tid; i < NPTS; i += 512) {
        float2 xy = *(const float2*)(drags + 2 * i);
        unsigned cell = (unsigned)((((int)xy.x) >> 6) * 8 + (((int)xy.y) >> 6));
        unsigned pos = atomicAdd(&cursm[cell], 1u);
        ordsm[pos] = (unsigned short)i;
    }
    __syncthreads();

    // per-lane bias registers: lane owns cols [4l,4l+4) and [128+4l,128+4l+4)
    u64 b1r0 = *(const u64*)(b1 + 4 * l);
    u64 b1r1 = *(const u64*)(b1 + 4 * l + 2);
    u64 b2r[4];
    b2r[0] = *(const u64*)(b2 + 4 * l);
    b2r[1] = *(const u64*)(b2 + 4 * l + 2);
    b2r[2] = *(const u64*)(b2 + 128 + 4 * l);
    b2r[3] = *(const u64*)(b2 + 128 + 4 * l + 2);

    // warp w owns cells [4w, 4w+4)
    const unsigned pbeg = startsm[4 * w];
    const unsigned pend = startsm[4 * w + 4];
    float* myh1 = h1s + w * 1024;

    const float fr      = c_freq[l >> 2];
    const int   use_y   = l & 1;
    const int   use_cos = (l >> 1) & 1;

    u64 run0 = 0, run1 = 0, run2 = 0, run3 = 0;
    int cur_cell = -1;
    float* gbase = g_hsum + (size_t)sb * CELLS * D2;

    for (unsigned p0 = pbeg; p0 < pend; p0 += 8) {
        const int nv = (int)min(8u, pend - p0);
        float fv[8]; int cel[8];
        #pragma unroll
        for (int pp = 0; pp < 8; pp++) {
            float arg = 0.f;
            if (pp < nv) {
                int idx = (int)ordsm[p0 + pp];
                float2 xy = *(const float2*)(drags + 2 * idx);
                cel[pp] = (((int)xy.x) >> 6) * 8 + (((int)xy.y) >> 6);
                arg = (use_y ? xy.y : xy.x) * fr;
            } else cel[pp] = -1;
            fv[pp] = trig_red(arg, use_cos);
        }

        // ---- L1: lane owns cols [4l, 4l+4) ----
        u64 a1[8][2];
        #pragma unroll
        for (int pp = 0; pp < 8; pp++) { a1[pp][0] = b1r0; a1[pp][1] = b1r1; }
        #pragma unroll 4
        for (int k = 0; k < 32; k++) {
            ulonglong2 wv = *(const ulonglong2*)(W1s + k * 128 + 4 * l);
            #pragma unroll
            for (int pp = 0; pp < 8; pp++) {
                u64 f2 = dup2(__shfl_sync(0xffffffffu, fv[pp], k));
                a1[pp][0] = ffma2(f2, wv.x, a1[pp][0]);
                a1[pp][1] = ffma2(f2, wv.y, a1[pp][1]);
            }
        }
        #pragma unroll
        for (int pp = 0; pp < 8; pp++) {
            float2 v0 = un2(a1[pp][0]), v1 = un2(a1[pp][1]);
            float4 hv = make_float4(silu_f(v0.x), silu_f(v0.y),
                                    silu_f(v1.x), silu_f(v1.y));
            *(float4*)(myh1 + pp * 128 + 4 * l) = hv;
        }
        __syncwarp();

        // ---- L2: lane owns cols [4l,4l+4) and [128+4l,128+4l+4) ----
        u64 a2[8][4];
        #pragma unroll
        for (int pp = 0; pp < 8; pp++) {
            a2[pp][0] = b2r[0]; a2[pp][1] = b2r[1];
            a2[pp][2] = b2r[2]; a2[pp][3] = b2r[3];
        }
        #pragma unroll 2
        for (int kp = 0; kp < 64; kp++) {
            float2 hp[8];
            #pragma unroll
            for (int pp = 0; pp < 8; pp++)     // broadcast LDS.64
                hp[pp] = *(const float2*)(myh1 + pp * 128 + 2 * kp);
            #pragma unroll
            for (int s = 0; s < 2; s++) {
                const float* wr = W2s + (2 * kp + s) * 256;
                ulonglong2 wA = *(const ulonglong2*)(wr + 4 * l);
                ulonglong2 wB = *(const ulonglong2*)(wr + 128 + 4 * l);
                #pragma unroll
                for (int pp = 0; pp < 8; pp++) {
                    u64 hd = dup2(s ? hp[pp].y : hp[pp].x);
                    a2[pp][0] = ffma2(hd, wA.x, a2[pp][0]);
                    a2[pp][1] = ffma2(hd, wA.y, a2[pp][1]);
                    a2[pp][2] = ffma2(hd, wB.x, a2[pp][2]);
                    a2[pp][3] = ffma2(hd, wB.y, a2[pp][3]);
                }
            }
        }

        // ---- silu + run-accumulate (cell warp-uniform; sorted order) ----
        for (int pp = 0; pp < 8; pp++) {
            if (cel[pp] < 0) break;
            if (cel[pp] != cur_cell) {
                if (cur_cell >= 0) {
                    float* gp = gbase + (size_t)cur_cell * D2;
                    float2 v0 = un2(run0), v1 = un2(run1);
                    float2 v2 = un2(run2), v3 = un2(run3);
                    *(float4*)(gp + 4 * l)       = make_float4(v0.x, v0.y, v1.x, v1.y);
                    *(float4*)(gp + 128 + 4 * l) = make_float4(v2.x, v2.y, v3.x, v3.y);
                }
                cur_cell = cel[pp];
                run0 = run1 = run2 = run3 = 0;
            }
            run0 = fadd2(run0, silu2(a2[pp][0]));
            run1 = fadd2(run1, silu2(a2[pp][1]));
            run2 = fadd2(run2, silu2(a2[pp][2]));
            run3 = fadd2(run3, silu2(a2[pp][3]));
        }
        __syncwarp();
    }
    if (cur_cell >= 0) {
        float* gp = gbase + (size_t)cur_cell * D2;
        float2 v0 = un2(run0), v1 = un2(run1);
        float2 v2 = un2(run2), v3 = un2(run3);
        *(float4*)(gp + 4 * l)       = make_float4(v0.x, v0.y, v1.x, v1.y);
        *(float4*)(gp + 128 + 4 * l) = make_float4(v2.x, v2.y, v3.x, v3.y);
    }
    // zero-fill empty cells
    #pragma unroll
    for (int c = 4 * w; c < 4 * w + 4; c++) {
        if (cntsm[c] == 0u) {
            float* gp = gbase + (size_t)c * D2;
            float4 z = make_float4(0.f, 0.f, 0.f, 0.f);
            *(float4*)(gp + 4 * l)       = z;
            *(float4*)(gp + 128 + 4 * l) = z;
        }
    }
}

// ---------------- K2 smem layout ----------------
#define S2_W3T 0        // 131072 (64 rows * 512 f)
#define S2_HST 131072   // 66560  (256 * 65 f, padded transpose)
#define S2_B3  197632   // 2048
#define S2_CNT 199680   // 256
#define SMEM2  199936

// out = Hsum @ W3 + cnt*b3. Warp w owns cols [32w,32w+32); lane l owns
// cells l, l+32. W3 staged in smem, warp-uniform LDS.128 broadcasts.
__global__ __launch_bounds__(512, 1)
void k2_l3(const float* __restrict__ W3, const float* __restrict__ b3,
           float* __restrict__ out)
{
    extern __shared__ char smem[];
    float* w3t  = (float*)(smem + S2_W3T);
    float* Hst  = (float*)(smem + S2_HST);
    float* b3s  = (float*)(smem + S2_B3);
    float* cnts = (float*)(smem + S2_CNT);

    const int tid = threadIdx.x;
    const int w   = tid >> 5;
    const int l   = tid & 31;
    const int sb  = blockIdx.x;
    const int side = sb >> 6;
    const int bv   = sb & 63;

    // stage transposed H: Hst[k*65 + cell] = g_hsum[sb][cell][k]
    {
        const float* src = g_hsum + (size_t)sb * CELLS * D2;
        for (int base = tid; base < CELLS * D2; base += 512) {
            int cell = base >> 8;
            int k    = base & 255;
            Hst[k * 65 + cell] = src[base];
        }
        b3s[tid] = b3[tid];
        if (tid < 64) cnts[tid] = (float)g_cnt[sb * CELLS + tid];
    }

    u64 acc[2][16];
    #pragma unroll
    for (int h = 0; h < 2; h++)
        #pragma unroll
        for (int j = 0; j < 16; j++) acc[h][j] = 0ull;

    for (int kt = 0; kt < 4; kt++) {
        __syncthreads();
        {
            const float4* src = (const float4*)(W3 + (size_t)kt * 64 * D3);
            float4* dst = (float4*)w3t;
            #pragma unroll 4
            for (int i = tid; i < (64 * D3) / 4; i += 512) dst[i] = src[i];
        }
        __syncthreads();
        #pragma unroll 2
        for (int kk = 0; kk < 64; kk++) {
            const int k = kt * 64 + kk;
            u64 hd0 = dup2(Hst[k * 65 + l]);
            u64 hd1 = dup2(Hst[k * 65 + l + 32]);
            const float* wr = w3t + kk * D3 + 32 * w;
            #pragma unroll
            for (int j2 = 0; j2 < 8; j2++) {   // broadcast LDS.128
                ulonglong2 wv = *(const ulonglong2*)(wr + 4 * j2);
                acc[0][2 * j2]     = ffma2(hd0, wv.x, acc[0][2 * j2]);
                acc[0][2 * j2 + 1] = ffma2(hd0, wv.y, acc[0][2 * j2 + 1]);
                acc[1][2 * j2]     = ffma2(hd1, wv.x, acc[1][2 * j2]);
                acc[1][2 * j2 + 1] = ffma2(hd1, wv.y, acc[1][2 * j2 + 1]);
            }
        }
    }

    const float c0 = cnts[l], c1 = cnts[l + 32];
    float* outp = out + ((size_t)(bv * 1024 + side * 512)) * 64;
    #pragma unroll
    for (int j = 0; j < 16; j++) {
        int col = 32 * w + 2 * j;
        float bx = b3s[col], by = b3s[col + 1];
        float2 v0 = un2(acc[0][j]);
        float2 v1 = un2(acc[1][j]);
        outp[(size_t)col       * 64 + l]      = v0.x + c0 * bx;
        outp[(size_t)(col + 1) * 64 + l]      = v0.y + c0 * by;
        outp[(size_t)col       * 64 + l + 32] = v1.x + c1 * bx;
        outp[(size_t)(col + 1) * 64 + l + 32] = v1.y + c1 * by;
    }
}

extern "C" void kernel_launch(void* const* d_in, const int* in_sizes, int n_in,
                              void* d_out, int out_size)
{
    const float* ds = (const float*)d_in[0];
    const float* de = (const float*)d_in[1];
    const float* W1 = (const float*)d_in[2];
    const float* b1 = (const float*)d_in[3];
    const float* W2 = (const float*)d_in[4];
    const float* b2 = (const float*)d_in[5];
    const float* W3 = (const float*)d_in[6];
    const float* b3 = (const float*)d_in[7];
    float* out = (float*)d_out;

    cudaFuncSetAttribute(k1_embed_agg, cudaFuncAttributeMaxDynamicSharedMemorySize, SMEM1);
    cudaFuncSetAttribute(k2_l3,        cudaFuncAttributeMaxDynamicSharedMemorySize, SMEM2);

    k1_embed_agg<<<SBCNT, 512, SMEM1>>>(ds, de, W1, b1, W2, b2);
    k2_l3<<<SBCNT, 512, SMEM2>>>(W3, b3, out);
}

// round 5
// speedup vs baseline: 1.4736x; 1.2419x over previous
#include <cuda_runtime.h>
#include <math.h>

#define NPTS  1024
#define D2    256
#define D3    512
#define CELLS 64
#define SBCNT 128

__device__ float g_hsum[SBCNT * CELLS * D2];
__device__ int   g_cnt [SBCNT * CELLS];

__constant__ float c_freq[8] = {
    1.0f, 1.7782794100389228f, 3.1622776601683795f, 5.623413251903491f,
    10.0f, 17.782794100389228f, 31.622776601683793f, 56.23413251903491f
};

typedef unsigned long long u64;

__device__ __forceinline__ u64 pk2(float lo, float hi) {
    u64 r; asm("mov.b64 %0,{%1,%2};" : "=l"(r) : "f"(lo), "f"(hi)); return r;
}
__device__ __forceinline__ u64 dup2(float v) { return pk2(v, v); }
__device__ __forceinline__ u64 ffma2(u64 a, u64 b, u64 c) {
    u64 d; asm("fma.rn.f32x2 %0,%1,%2,%3;" : "=l"(d) : "l"(a), "l"(b), "l"(c)); return d;
}
__device__ __forceinline__ u64 fadd2(u64 a, u64 b) {
    u64 d; asm("add.rn.f32x2 %0,%1,%2;" : "=l"(d) : "l"(a), "l"(b)); return d;
}
__device__ __forceinline__ float2 un2(u64 v) {
    float2 f; asm("mov.b64 {%0,%1},%2;" : "=f"(f.x), "=f"(f.y) : "l"(v)); return f;
}
__device__ __forceinline__ float silu_f(float v) {
    return __fdividef(v, 1.0f + __expf(-v));
}
__device__ __forceinline__ u64 silu2(u64 a) {
    float2 v = un2(a); return pk2(silu_f(v.x), silu_f(v.y));
}
// Cody-Waite mod-2pi then MUFU trig (arg reduced to [-pi,pi])
__device__ __forceinline__ float trig_red(float arg, int use_cos) {
    const float INV2PI = 0.15915494309189535f;
    const float C_HI   = 6.2831854820251465f;
    const float C_LO   = -1.7484556e-7f;
    float q = rintf(arg * INV2PI);
    float r = __fmaf_rn(-q, C_HI, arg);
    r = __fmaf_rn(-q, C_LO, r);
    return use_cos ? __cosf(r) : __sinf(r);
}

// ---------------- K1 smem layout (bytes) ----------------
#define S1_W2    0          // 131072
#define S1_W1    131072     // 16384
#define S1_H1    147456     // 65536  (16 warps * 8 pts * 128 f)
#define S1_ORD   212992     // 2048   (u16[1024])
#define S1_CNT   215040     // 256
#define S1_START 215296     // 272
#define S1_CUR   215568     // 256
#define SMEM1    215824

__global__ __launch_bounds__(512, 1)
void k1_embed_agg(const float* __restrict__ ds, const float* __restrict__ de,
                  const float* __restrict__ W1, const float* __restrict__ b1,
                  const float* __restrict__ W2, const float* __restrict__ b2)
{
    extern __shared__ char smem[];
    float*          W2s    = (float*)(smem + S1_W2);
    float*          W1s    = (float*)(smem + S1_W1);
    float*          h1s    = (float*)(smem + S1_H1);
    unsigned short* ordsm  = (unsigned short*)(smem + S1_ORD);
    unsigned*       cntsm  = (unsigned*)(smem + S1_CNT);
    unsigned*       startsm= (unsigned*)(smem + S1_START);
    unsigned*       cursm  = (unsigned*)(smem + S1_CUR);

    const int tid = threadIdx.x;
    const int w   = tid >> 5;
    const int l   = tid & 31;
    const int sb  = blockIdx.x;
    const int side = sb >> 6;
    const int bv   = sb & 63;
    const float* __restrict__ drags = (side ? de : ds) + (size_t)bv * NPTS * 2;
    float* gbase = g_hsum + (size_t)sb * CELLS * D2;

    // stage W2, W1; zero counters; zero this block's g_hsum slice
    {
        const float4* src2 = (const float4*)W2;
        float4* dst2 = (float4*)W2s;
        #pragma unroll 4
        for (int i = tid; i < (128 * 256) / 4; i += 512) dst2[i] = src2[i];
        const float4* src1 = (const float4*)W1;
        float4* dst1 = (float4*)W1s;
        #pragma unroll
        for (int i = tid; i < (32 * 128) / 4; i += 512) dst1[i] = src1[i];
        float4* gz = (float4*)gbase;
        #pragma unroll
        for (int i = tid; i < (CELLS * D2) / 4; i += 512)
            gz[i] = make_float4(0.f, 0.f, 0.f, 0.f);
        if (tid < 64) cntsm[tid] = 0u;
    }
    __syncthreads();

    // counting sort: pass 1
    #pragma unroll
    for (int i = tid; i < NPTS; i += 512) {
        float2 xy = *(const float2*)(drags + 2 * i);
        unsigned cell = (unsigned)((((int)xy.x) >> 6) * 8 + (((int)xy.y) >> 6));
        atomicAdd(&cntsm[cell], 1u);
    }
    __syncthreads();
    if (tid == 0) {
        unsigned run = 0;
        for (int c = 0; c < CELLS; c++) { startsm[c] = run; run += cntsm[c]; }
        startsm[CELLS] = run;
    }
    __syncthreads();
    if (tid < 64) {
        cursm[tid] = startsm[tid];
        g_cnt[sb * CELLS + tid] = (int)cntsm[tid];
    }
    __syncthreads();
    // pass 2: scatter to sorted order
    #pragma unroll
    for (int i = tid; i < NPTS; i += 512) {
        float2 xy = *(const float2*)(drags + 2 * i);
        unsigned cell = (unsigned)((((int)xy.x) >> 6) * 8 + (((int)xy.y) >> 6));
        unsigned pos = atomicAdd(&cursm[cell], 1u);
        ordsm[pos] = (unsigned short)i;
    }
    __syncthreads();

    // per-lane bias registers: lane owns cols [4l,4l+4) and [128+4l,128+4l+4)
    u64 b1r0 = *(const u64*)(b1 + 4 * l);
    u64 b1r1 = *(const u64*)(b1 + 4 * l + 2);
    u64 b2r[4];
    b2r[0] = *(const u64*)(b2 + 4 * l);
    b2r[1] = *(const u64*)(b2 + 4 * l + 2);
    b2r[2] = *(const u64*)(b2 + 128 + 4 * l);
    b2r[3] = *(const u64*)(b2 + 128 + 4 * l + 2);

    // perfectly balanced: warp w processes sorted points [64w, 64w+64)
    float* myh1 = h1s + w * 1024;

    const float fr      = c_freq[l >> 2];
    const int   use_y   = l & 1;
    const int   use_cos = (l >> 1) & 1;

    u64 run0 = 0, run1 = 0, run2 = 0, run3 = 0;
    int cur_cell = -1;

    #pragma unroll 1
    for (int p0 = 64 * w; p0 < 64 * w + 64; p0 += 8) {
        float fv[8]; int cel[8];
        #pragma unroll
        for (int pp = 0; pp < 8; pp++) {
            int idx = (int)ordsm[p0 + pp];
            float2 xy = *(const float2*)(drags + 2 * idx);
            cel[pp] = (((int)xy.x) >> 6) * 8 + (((int)xy.y) >> 6);
            fv[pp] = trig_red((use_y ? xy.y : xy.x) * fr, use_cos);
        }

        // ---- L1: lane owns cols [4l, 4l+4) ----
        u64 a1[8][2];
        #pragma unroll
        for (int pp = 0; pp < 8; pp++) { a1[pp][0] = b1r0; a1[pp][1] = b1r1; }
        #pragma unroll 4
        for (int k = 0; k < 32; k++) {
            ulonglong2 wv = *(const ulonglong2*)(W1s + k * 128 + 4 * l);
            #pragma unroll
            for (int pp = 0; pp < 8; pp++) {
                u64 f2 = dup2(__shfl_sync(0xffffffffu, fv[pp], k));
                a1[pp][0] = ffma2(f2, wv.x, a1[pp][0]);
                a1[pp][1] = ffma2(f2, wv.y, a1[pp][1]);
            }
        }
        #pragma unroll
        for (int pp = 0; pp < 8; pp++) {
            float2 v0 = un2(a1[pp][0]), v1 = un2(a1[pp][1]);
            float4 hv = make_float4(silu_f(v0.x), silu_f(v0.y),
                                    silu_f(v1.x), silu_f(v1.y));
            *(float4*)(myh1 + pp * 128 + 4 * l) = hv;
        }
        __syncwarp();

        // ---- L2: lane owns cols [4l,4l+4) and [128+4l,128+4l+4) ----
        u64 a2[8][4];
        #pragma unroll
        for (int pp = 0; pp < 8; pp++) {
            a2[pp][0] = b2r[0]; a2[pp][1] = b2r[1];
            a2[pp][2] = b2r[2]; a2[pp][3] = b2r[3];
        }
        #pragma unroll 2
        for (int kp = 0; kp < 64; kp++) {
            float2 hp[8];
            #pragma unroll
            for (int pp = 0; pp < 8; pp++)     // broadcast LDS.64
                hp[pp] = *(const float2*)(myh1 + pp * 128 + 2 * kp);
            #pragma unroll
            for (int s = 0; s < 2; s++) {
                const float* wr = W2s + (2 * kp + s) * 256;
                ulonglong2 wA = *(const ulonglong2*)(wr + 4 * l);
                ulonglong2 wB = *(const ulonglong2*)(wr + 128 + 4 * l);
                #pragma unroll
                for (int pp = 0; pp < 8; pp++) {
                    u64 hd = dup2(s ? hp[pp].y : hp[pp].x);
                    a2[pp][0] = ffma2(hd, wA.x, a2[pp][0]);
                    a2[pp][1] = ffma2(hd, wA.y, a2[pp][1]);
                    a2[pp][2] = ffma2(hd, wB.x, a2[pp][2]);
                    a2[pp][3] = ffma2(hd, wB.y, a2[pp][3]);
                }
            }
        }

        // ---- silu + run-accumulate; flush via RED (cross-warp cells safe) ----
        #pragma unroll
        for (int pp = 0; pp < 8; pp++) {
            if (cel[pp] != cur_cell) {
                if (cur_cell >= 0) {
                    float* gp = gbase + (size_t)cur_cell * D2;
                    float2 v0 = un2(run0), v1 = un2(run1);
                    float2 v2 = un2(run2), v3 = un2(run3);
                    atomicAdd(gp + 4 * l,           v0.x);
                    atomicAdd(gp + 4 * l + 1,       v0.y);
                    atomicAdd(gp + 4 * l + 2,       v1.x);
                    atomicAdd(gp + 4 * l + 3,       v1.y);
                    atomicAdd(gp + 128 + 4 * l,     v2.x);
                    atomicAdd(gp + 128 + 4 * l + 1, v2.y);
                    atomicAdd(gp + 128 + 4 * l + 2, v3.x);
                    atomicAdd(gp + 128 + 4 * l + 3, v3.y);
                }
                cur_cell = cel[pp];
                run0 = run1 = run2 = run3 = 0;
            }
            run0 = fadd2(run0, silu2(a2[pp][0]));
            run1 = fadd2(run1, silu2(a2[pp][1]));
            run2 = fadd2(run2, silu2(a2[pp][2]));
            run3 = fadd2(run3, silu2(a2[pp][3]));
        }
        __syncwarp();
    }
    if (cur_cell >= 0) {
        float* gp = gbase + (size_t)cur_cell * D2;
        float2 v0 = un2(run0), v1 = un2(run1);
        float2 v2 = un2(run2), v3 = un2(run3);
        atomicAdd(gp + 4 * l,           v0.x);
        atomicAdd(gp + 4 * l + 1,       v0.y);
        atomicAdd(gp + 4 * l + 2,       v1.x);
        atomicAdd(gp + 4 * l + 3,       v1.y);
        atomicAdd(gp + 128 + 4 * l,     v2.x);
        atomicAdd(gp + 128 + 4 * l + 1, v2.y);
        atomicAdd(gp + 128 + 4 * l + 2, v3.x);
        atomicAdd(gp + 128 + 4 * l + 3, v3.y);
    }
}

// ---------------- K2 smem layout ----------------
#define S2_W3T 0        // 131072 (64 rows * 512 f)
#define S2_HST 131072   // 66560  (256 * 65 f, padded transpose)
#define S2_B3  197632   // 2048
#define S2_CNT 199680   // 256
#define SMEM2  199936

// out = Hsum @ W3 + cnt*b3. Warp w owns cols [32w,32w+32); lane l owns
// cells l, l+32. W3 staged in smem, warp-uniform LDS.128 broadcasts.
__global__ __launch_bounds__(512, 1)
void k2_l3(const float* __restrict__ W3, const float* __restrict__ b3,
           float* __restrict__ out)
{
    extern __shared__ char smem[];
    float* w3t  = (float*)(smem + S2_W3T);
    float* Hst  = (float*)(smem + S2_HST);
    float* b3s  = (float*)(smem + S2_B3);
    float* cnts = (float*)(smem + S2_CNT);

    const int tid = threadIdx.x;
    const int w   = tid >> 5;
    const int l   = tid & 31;
    const int sb  = blockIdx.x;
    const int side = sb >> 6;
    const int bv   = sb & 63;

    // stage transposed H: Hst[k*65 + cell] = g_hsum[sb][cell][k]
    {
        const float* src = g_hsum + (size_t)sb * CELLS * D2;
        for (int base = tid; base < CELLS * D2; base += 512) {
            int cell = base >> 8;
            int k    = base & 255;
            Hst[k * 65 + cell] = src[base];
        }
        b3s[tid] = b3[tid];
        if (tid < 64) cnts[tid] = (float)g_cnt[sb * CELLS + tid];
    }

    u64 acc[2][16];
    #pragma unroll
    for (int h = 0; h < 2; h++)
        #pragma unroll
        for (int j = 0; j < 16; j++) acc[h][j] = 0ull;

    for (int kt = 0; kt < 4; kt++) {
        __syncthreads();
        {
            const float4* src = (const float4*)(W3 + (size_t)kt * 64 * D3);
            float4* dst = (float4*)w3t;
            #pragma unroll 4
            for (int i = tid; i < (64 * D3) / 4; i += 512) dst[i] = src[i];
        }
        __syncthreads();
        #pragma unroll 2
        for (int kk = 0; kk < 64; kk++) {
            const int k = kt * 64 + kk;
            u64 hd0 = dup2(Hst[k * 65 + l]);
            u64 hd1 = dup2(Hst[k * 65 + l + 32]);
            const float* wr = w3t + kk * D3 + 32 * w;
            #pragma unroll
            for (int j2 = 0; j2 < 8; j2++) {   // broadcast LDS.128
                ulonglong2 wv = *(const ulonglong2*)(wr + 4 * j2);
                acc[0][2 * j2]     = ffma2(hd0, wv.x, acc[0][2 * j2]);
                acc[0][2 * j2 + 1] = ffma2(hd0, wv.y, acc[0][2 * j2 + 1]);
                acc[1][2 * j2]     = ffma2(hd1, wv.x, acc[1][2 * j2]);
                acc[1][2 * j2 + 1] = ffma2(hd1, wv.y, acc[1][2 * j2 + 1]);
            }
        }
    }

    const float c0 = cnts[l], c1 = cnts[l + 32];
    float* outp = out + ((size_t)(bv * 1024 + side * 512)) * 64;
    #pragma unroll
    for (int j = 0; j < 16; j++) {
        int col = 32 * w + 2 * j;
        float bx = b3s[col], by = b3s[col + 1];
        float2 v0 = un2(acc[0][j]);
        float2 v1 = un2(acc[1][j]);
        outp[(size_t)col       * 64 + l]      = v0.x + c0 * bx;
        outp[(size_t)(col + 1) * 64 + l]      = v0.y + c0 * by;
        outp[(size_t)col       * 64 + l + 32] = v1.x + c1 * bx;
        outp[(size_t)(col + 1) * 64 + l + 32] = v1.y + c1 * by;
    }
}

extern "C" void kernel_launch(void* const* d_in, const int* in_sizes, int n_in,
                              void* d_out, int out_size)
{
    const float* ds = (const float*)d_in[0];
    const float* de = (const float*)d_in[1];
    const float* W1 = (const float*)d_in[2];
    const float* b1 = (const float*)d_in[3];
    const float* W2 = (const float*)d_in[4];
    const float* b2 = (const float*)d_in[5];
    const float* W3 = (const float*)d_in[6];
    const float* b3 = (const float*)d_in[7];
    float* out = (float*)d_out;

    cudaFuncSetAttribute(k1_embed_agg, cudaFuncAttributeMaxDynamicSharedMemorySize, SMEM1);
    cudaFuncSetAttribute(k2_l3,        cudaFuncAttributeMaxDynamicSharedMemorySize, SMEM2);

    k1_embed_agg<<<SBCNT, 512, SMEM1>>>(ds, de, W1, b1, W2, b2);
    k2_l3<<<SBCNT, 512, SMEM2>>>(W3, b3, out);
}